// round 16
// baseline (speedup 1.0000x reference)
#include <cuda_runtime.h>
#include <math.h>

#define Bn 8
#define Hn 192
#define Wn 192
#define NTOT (Bn*Hn*Wn)
#define NCH 6                     // 192 rows = 6 x u32 words
#define BIGD (1 << 20)

typedef unsigned long long ull;

__device__ unsigned g_mask[2][Bn][NCH][Wn];   // fg bit per (row chunk, col)
__device__ int      g_hasany[2][Bn][NCH];
// signed column-dist^2 field: |v| = dist^2 to nearest opposite-class pixel in
// the column (1e12 sentinel if none); sign bit = pixel class (1 = fg)
__device__ float    g_cd[2][Bn][Hn][Wn];
__device__ float    g_part[Bn*Hn];
__device__ unsigned g_count = 0;

// ---------------------------------------------------------------------------
// Kernel A: per-column fg bitmasks (R13 layout, coalesced stores).
// ---------------------------------------------------------------------------
__global__ void mask_kernel(const float* __restrict__ pred,
                            const float* __restrict__ tgt) {
    const int blk = blockIdx.x;               // t*48 + b*6 + chunk
    const int t = blk / (Bn * NCH);
    const int r = blk % (Bn * NCH);
    const int b = r / NCH;
    const int chunk = r % NCH;
    const float* src = t ? tgt : pred;
    const int w = threadIdx.x;
    const int y = threadIdx.y;                // 0 = low 16 rows, 1 = high 16
    const int h0 = chunk * 32 + y * 16;

    unsigned part = 0;
    #pragma unroll
    for (int i = 0; i < 16; ++i) {
        float v = src[(b * Hn + h0 + i) * Wn + w];
        bool fg = t ? (v > 0.5f) : (v > 0.0f);   // sigmoid(v)>0.5 <=> v>0
        part |= (unsigned)fg << i;
    }

    __shared__ unsigned sm[Wn];
    if (y == 0) sm[w] = part;
    int any = __syncthreads_or(part != 0u);
    if (y == 1) g_mask[t][b][chunk][w] = sm[w] | (part << 16);
    if (w == 0 && y == 0) g_hasany[t][b][chunk] = any;
}

__device__ __forceinline__ unsigned sel6(unsigned w0, unsigned w1, unsigned w2,
                                         unsigned w3, unsigned w4, unsigned w5,
                                         int k) {
    return (k == 0) ? w0 : (k == 1) ? w1 : (k == 2) ? w2 :
           (k == 3) ? w3 : (k == 4) ? w4 : (k == 5) ? w5 : 0u;
}

// exact full-range fallback: nearest set bit of 192-bit mask from row h
__device__ __forceinline__ int nearest_set3(ull m0, ull m1, ull m2,
                                            int c, int bit) {
    ull a   = (c == 0) ? m0 : ((c == 1) ? m1 : m2);
    ull dn1 = (c == 0) ? m1 : ((c == 1) ? m2 : 0ULL);
    ull dn2 = (c == 0) ? m2 : 0ULL;
    ull up1 = (c == 2) ? m1 : ((c == 1) ? m0 : 0ULL);
    ull up2 = (c == 2) ? m0 : 0ULL;

    int down, up;
    ull x = a & (~0ULL << bit);
    if (x)        down = __ffsll(x) - 1 - bit;
    else if (dn1) down = 64  + __ffsll(dn1) - 1 - bit;
    else if (dn2) down = 128 + __ffsll(dn2) - 1 - bit;
    else          down = BIGD;

    x = a << (63 - bit);
    if (x)        up = __clzll(x);
    else if (up1) up = bit + 1  + __clzll(up1);
    else if (up2) up = bit + 65 + __clzll(up2);
    else          up = BIGD;

    return min(up, down);
}

// ---------------------------------------------------------------------------
// Kernel A2: column distance field. Block = (tensor, b, chunk), dim (192,2);
// thread (w,y) computes 16 rows of column w incrementally from two 64-bit
// windows (A = this|next word, B = prev|this word): per row 2 xor-selects,
// 2 shifts, ffsll/clzll -> exact if opposite bit within +-32 (covers all but
// astronomically rare runs; exact fallback otherwise). Stores coalesced.
// ---------------------------------------------------------------------------
__global__ void colsdist_kernel() {
    const int blk = blockIdx.x;               // t*48 + b*6 + chunk
    const int t = blk / (Bn * NCH);
    const int r = blk % (Bn * NCH);
    const int b = r / NCH;
    const int chunk = r % NCH;
    const int w = threadIdx.x;
    const int y = threadIdx.y;

    const unsigned m0 = g_mask[t][b][0][w];
    const unsigned m1 = g_mask[t][b][1][w];
    const unsigned m2 = g_mask[t][b][2][w];
    const unsigned m3 = g_mask[t][b][3][w];
    const unsigned m4 = g_mask[t][b][4][w];
    const unsigned m5 = g_mask[t][b][5][w];

    const unsigned wp = sel6(m0, m1, m2, m3, m4, m5, chunk - 1);
    const unsigned wc = sel6(m0, m1, m2, m3, m4, m5, chunk);
    const unsigned wn = sel6(m0, m1, m2, m3, m4, m5, chunk + 1);

    const ull A = (ull)wc | ((ull)wn << 32);   // rows h0 .. h0+63
    const ull B = (ull)wp | ((ull)wc << 32);   // rows h0-32 .. h0+31
    const ull vA = (chunk == NCH - 1) ? 0x00000000FFFFFFFFULL : ~0ULL;
    const ull vB = (chunk == 0)       ? 0xFFFFFFFF00000000ULL : ~0ULL;

    #pragma unroll
    for (int i = 0; i < 16; ++i) {
        const int rr = y * 16 + i;             // row within chunk, 0..31
        const int h = chunk * 32 + rr;
        const unsigned cls = (wc >> rr) & 1u;
        const ull s = 0ULL - (ull)cls;         // 0 or ~0: search opposite class

        const ull xd = ((A ^ s) & vA) >> (rr + 1);        // rows > h
        const ull xu = ((B ^ s) & vB) << (32 - rr);       // rows < h, MSB = h-1
        int down = xd ? __ffsll((long long)xd)       : 999;
        int up   = xu ? (__clzll((long long)xu) + 1) : 999;
        int d = min(down, up);

        float dsq;
        if (d < 999) {
            dsq = (float)(d * d);
        } else {                                // rare: exact full-column scan
            ull f0 = (((ull)m0 | ((ull)m1 << 32)) ^ s);
            ull f1 = (((ull)m2 | ((ull)m3 << 32)) ^ s);
            ull f2 = (((ull)m4 | ((ull)m5 << 32)) ^ s);
            int dd = nearest_set3(f0, f1, f2, h >> 6, h & 63);
            dsq = (dd >= BIGD) ? 1.0e12f : (float)(dd * dd);
        }
        g_cd[t][b][h][w] = __uint_as_float(__float_as_uint(dsq) | (cls << 31));
    }
}

// ---------------------------------------------------------------------------
// Kernel B: load signed column-dist^2 (1 f32 per tensor), windowed exact
// 1D row DT, fused loss + deterministic reduction + last-block final reduce.
// ---------------------------------------------------------------------------
__global__ void rowpass_kernel(const float* __restrict__ pred,
                               const float* __restrict__ tgt,
                               float* __restrict__ out) {
    const int b = blockIdx.x / Hn;
    const int h = blockIdx.x % Hn;
    const int p = threadIdx.x;

    __shared__ float ssq[4][3 * Wn];            // [class][pad | data | pad]
    __shared__ float wsum[6];
    __shared__ int   s_last;

    // prefetch all globals early
    const int idx = (b * Hn + h) * Wn + p;
    const float x  = pred[idx];
    const float tv = tgt[idx];
    const unsigned uP = __float_as_uint(g_cd[0][b][h][p]);
    const unsigned uT = __float_as_uint(g_cd[1][b][h][p]);
    int hp = 0, ht = 0;
    #pragma unroll
    for (int j = 0; j < NCH; ++j) {
        hp |= g_hasany[0][b][j];
        ht |= g_hasany[1][b][j];
    }

    // pad borders (sentinel larger than any real candidate)
    #pragma unroll
    for (int k = 0; k < 4; ++k) {
        ssq[k][p]        = 1.0e12f;
        ssq[k][p + 2*Wn] = 1.0e12f;
    }

    const bool fgP = (uP >> 31) != 0u;
    const bool fgT = (uT >> 31) != 0u;
    const float dsqP = __uint_as_float(uP & 0x7FFFFFFFu);
    const float dsqT = __uint_as_float(uT & 0x7FFFFFFFu);

    ssq[0][Wn + p] = fgP ? dsqP : 0.0f;         // pred fg-EDT col dist^2
    ssq[1][Wn + p] = fgP ? 0.0f : dsqP;         // pred bg-EDT col dist^2
    ssq[2][Wn + p] = fgT ? dsqT : 0.0f;
    ssq[3][Wn + p] = fgT ? 0.0f : dsqT;
    __syncthreads();

    const float* aP = (fgP ? ssq[0] : ssq[1]) + Wn + p;
    const float* aT = (fgT ? ssq[2] : ssq[3]) + Wn + p;
    float bp = aP[0];
    float bt = aT[0];

    // branchless speculative window d = 1..4
    #pragma unroll
    for (int d = 1; d <= 4; ++d) {
        float dd = (float)(d * d);
        bp = fminf(bp, dd + fminf(aP[-d], aP[d]));
        bt = fminf(bt, dd + fminf(aT[-d], aT[d]));
    }
    float bmax = fmaxf(bp, bt);

    // residual: exact break d^2 >= bmax
    if (bmax > 25.0f) {
        for (int d = 5; d < Wn; ++d) {
            float dd = (float)(d * d);
            if (dd >= bmax) break;
            bp = fminf(bp, dd + fminf(aP[-d], aP[d]));
            bt = fminf(bt, dd + fminf(aT[-d], aT[d]));
            bmax = fmaxf(bp, bt);
        }
    }

    // other-class D is exactly 0 -> field = sqrt(D_own)
    float pd = sqrtf(bp) * (float)(hp != 0);
    float td = sqrtf(bt) * (float)(ht != 0);

    float sg = 1.0f / (1.0f + __expf(-x));
    float e  = sg - tv;
    e = e * e;

    float num = pd * pd + td * td;
    float den = pd + td;
    den = den * den;
    float v = e * (num / den);

    // deterministic block reduction
    #pragma unroll
    for (int o = 16; o > 0; o >>= 1)
        v += __shfl_down_sync(0xffffffffu, v, o);
    if ((p & 31) == 0) wsum[p >> 5] = v;
    __syncthreads();
    if (p == 0) {
        float s = 0.0f;
        #pragma unroll
        for (int i = 0; i < 6; ++i) s += wsum[i];
        __stcg(&g_part[blockIdx.x], s);         // straight to L2
        unsigned ticket;
        asm volatile("atom.acq_rel.gpu.global.add.u32 %0, [%1], %2;"
                     : "=r"(ticket)
                     : "l"(&g_count), "r"(1u)
                     : "memory");
        s_last = (ticket == (unsigned)(gridDim.x - 1));
    }
    __syncthreads();

    // last finishing block: deterministic fixed-order fp64 final reduction.
    if (s_last) {
        __shared__ double dsm[Wn];
        double s = 0.0;
        for (int i = p; i < Bn * Hn; i += Wn)
            s += (double)__ldcg(&g_part[i]);
        dsm[p] = s;
        __syncthreads();
        #pragma unroll
        for (int o = 96; o >= 3; o >>= 1) {     // 192->96->...->3
            if (p < o) dsm[p] += dsm[p + o];
            __syncthreads();
        }
        if (p == 0) {
            double tot = dsm[0] + dsm[1] + dsm[2];
            out[0] = (float)(tot / (double)NTOT);
            g_count = 0;
        }
    }
}

extern "C" void kernel_launch(void* const* d_in, const int* in_sizes, int n_in,
                              void* d_out, int out_size) {
    const float* pred = (const float*)d_in[0];
    const float* tgt  = (const float*)d_in[1];
    float* out = (float*)d_out;
    (void)in_sizes; (void)n_in; (void)out_size;

    dim3 mb(Wn, 2);
    mask_kernel<<<2 * Bn * NCH, mb>>>(pred, tgt);
    colsdist_kernel<<<2 * Bn * NCH, mb>>>();
    rowpass_kernel<<<Bn * Hn, Wn>>>(pred, tgt, out);
}

// round 17
// speedup vs baseline: 1.1820x; 1.1820x over previous
#include <cuda_runtime.h>
#include <math.h>

#define Bn 8
#define Hn 192
#define Wn 192
#define NTOT (Bn*Hn*Wn)
#define NCH 6                     // 192 rows = 6 x u32 words
#define ROWS 6                    // rows per rowpass block
#define NSL (Hn / ROWS)           // 32 slices
#define BIGD (1 << 20)

typedef unsigned long long ull;

__device__ unsigned g_mask[2][Bn][NCH][Wn];   // fg bit per (row chunk, col)
__device__ int      g_hasany[2][Bn][NCH];
__device__ float    g_part[Bn*NSL];
__device__ unsigned g_count = 0;

// ---------------------------------------------------------------------------
// Kernel A: per-column fg bitmasks (proven R13 form).
// ---------------------------------------------------------------------------
__global__ void mask_kernel(const float* __restrict__ pred,
                            const float* __restrict__ tgt) {
    const int blk = blockIdx.x;               // t*48 + b*6 + chunk
    const int t = blk / (Bn * NCH);
    const int r = blk % (Bn * NCH);
    const int b = r / NCH;
    const int chunk = r % NCH;
    const float* src = t ? tgt : pred;
    const int w = threadIdx.x;
    const int y = threadIdx.y;                // 0 = low 16 rows, 1 = high 16
    const int h0 = chunk * 32 + y * 16;

    unsigned part = 0;
    #pragma unroll
    for (int i = 0; i < 16; ++i) {
        float v = src[(b * Hn + h0 + i) * Wn + w];
        bool fg = t ? (v > 0.5f) : (v > 0.0f);   // sigmoid(v)>0.5 <=> v>0
        part |= (unsigned)fg << i;
    }

    __shared__ unsigned sm[Wn];
    if (y == 0) sm[w] = part;
    int any = __syncthreads_or(part != 0u);
    if (y == 1) g_mask[t][b][chunk][w] = sm[w] | (part << 16);
    if (w == 0 && y == 0) g_hasany[t][b][chunk] = any;
}

// exact full-range fallback: nearest set bit of 192-bit mask from row h
__device__ __forceinline__ int nearest_set3(ull m0, ull m1, ull m2,
                                            int c, int bit) {
    ull a   = (c == 0) ? m0 : ((c == 1) ? m1 : m2);
    ull dn1 = (c == 0) ? m1 : ((c == 1) ? m2 : 0ULL);
    ull dn2 = (c == 0) ? m2 : 0ULL;
    ull up1 = (c == 2) ? m1 : ((c == 1) ? m0 : 0ULL);
    ull up2 = (c == 2) ? m0 : 0ULL;

    int down, up;
    ull x = a & (~0ULL << bit);
    if (x)        down = __ffsll(x) - 1 - bit;
    else if (dn1) down = 64  + __ffsll(dn1) - 1 - bit;
    else if (dn2) down = 128 + __ffsll(dn2) - 1 - bit;
    else          down = BIGD;

    x = a << (63 - bit);
    if (x)        up = __clzll(x);
    else if (up1) up = bit + 1  + __clzll(up1);
    else if (up2) up = bit + 65 + __clzll(up2);
    else          up = BIGD;

    return min(up, down);
}

// column dist^2 to nearest opposite-class pixel at row h (c=h>>6, bit=h&63,
// both uniform per call site). 64-bit reach each direction via two windows;
// exact fallback when both empty (rare). H=192=3x64 exactly -> no pad bits.
__device__ __forceinline__ float cdist_sq(ull m0, ull m1, ull m2,
                                          int c, int bit, bool& fg_out) {
    ull a  = (c == 0) ? m0 : ((c == 1) ? m1 : m2);
    ull dn = (c == 0) ? m1 : ((c == 1) ? m2 : 0ULL);
    ull up = (c == 0) ? 0ULL : ((c == 1) ? m0 : m1);

    const bool fg = (a >> bit) & 1ULL;
    fg_out = fg;
    const ull s = fg ? ~0ULL : 0ULL;
    const ull A  = a ^ s;
    const ull DN = (c == 2) ? 0ULL : (dn ^ s);
    const ull UP = (c == 0) ? 0ULL : (up ^ s);

    // xd bit k = row h+1+k ; xu bit (63-k) = row h-1-k
    const ull xd = ((A >> bit) >> 1) | (DN << (63 - bit));
    const ull xu = ((A << (63 - bit)) << 1) | ((UP >> bit) >> 1);

    int down = xd ? __ffsll((long long)xd)       : 999;
    int u    = xu ? (__clzll((long long)xu) + 1) : 999;
    int d = min(down, u);
    if (d < 999) return (float)(d * d);

    // rare: nothing within +-64 rows -> exact full scan on flipped mask
    int dd = nearest_set3(m0 ^ s, m1 ^ s, m2 ^ s, c, bit);
    return (dd >= BIGD) ? 1.0e12f : (float)(dd * dd);
}

// ---------------------------------------------------------------------------
// Kernel B: 6 rows per block. Masks loaded ONCE per thread (registers), then
// per row: column dist (two 64-bit windows), double-buffered smem ssq (one
// barrier per row), exact windowed row DT, fused loss; single reduction at
// the end + ticket + last-block deterministic fp64 final reduce.
// ---------------------------------------------------------------------------
__global__ void rowpass_kernel(const float* __restrict__ pred,
                               const float* __restrict__ tgt,
                               float* __restrict__ out) {
    const int b  = blockIdx.x >> 5;            // / NSL
    const int sl = blockIdx.x & 31;            // % NSL
    const int h0 = sl * ROWS;
    const int p  = threadIdx.x;

    __shared__ float ssq[2][4][3 * Wn];        // [buf][class][pad|data|pad]
    __shared__ float wsum[6];
    __shared__ double dsm[Wn];
    __shared__ int   s_last;

    // column masks, loaded once (12 coalesced u32 LDG)
    ull mp0, mp1, mp2, mt0, mt1, mt2;
    {
        const unsigned* gp = &g_mask[0][b][0][p];
        const unsigned* gt = &g_mask[1][b][0][p];
        mp0 = (ull)gp[0*Wn] | ((ull)gp[1*Wn] << 32);
        mp1 = (ull)gp[2*Wn] | ((ull)gp[3*Wn] << 32);
        mp2 = (ull)gp[4*Wn] | ((ull)gp[5*Wn] << 32);
        mt0 = (ull)gt[0*Wn] | ((ull)gt[1*Wn] << 32);
        mt1 = (ull)gt[2*Wn] | ((ull)gt[3*Wn] << 32);
        mt2 = (ull)gt[4*Wn] | ((ull)gt[5*Wn] << 32);
    }

    // prefetch loss inputs for all rows (independent LDG, high MLP)
    float xs[ROWS], tvs[ROWS];
    #pragma unroll
    for (int r = 0; r < ROWS; ++r) {
        const int idx = (b * Hn + h0 + r) * Wn + p;
        xs[r]  = pred[idx];
        tvs[r] = tgt[idx];
    }

    int hp = 0, ht = 0;
    #pragma unroll
    for (int j = 0; j < NCH; ++j) {
        hp |= g_hasany[0][b][j];
        ht |= g_hasany[1][b][j];
    }

    // pad borders once (both buffers)
    #pragma unroll
    for (int bu = 0; bu < 2; ++bu)
        #pragma unroll
        for (int k = 0; k < 4; ++k) {
            ssq[bu][k][p]        = 1.0e12f;
            ssq[bu][k][p + 2*Wn] = 1.0e12f;
        }
    __syncthreads();

    float vsum = 0.0f;

    #pragma unroll
    for (int r = 0; r < ROWS; ++r) {
        const int h = h0 + r;
        const int c = h >> 6, bit = h & 63;    // uniform
        const int bu = r & 1;

        bool fgP, fgT;
        const float dsqP = cdist_sq(mp0, mp1, mp2, c, bit, fgP);
        const float dsqT = cdist_sq(mt0, mt1, mt2, c, bit, fgT);

        ssq[bu][0][Wn + p] = fgP ? dsqP : 0.0f;
        ssq[bu][1][Wn + p] = fgP ? 0.0f : dsqP;
        ssq[bu][2][Wn + p] = fgT ? dsqT : 0.0f;
        ssq[bu][3][Wn + p] = fgT ? 0.0f : dsqT;
        __syncthreads();                        // one barrier per row

        const float* aP = (fgP ? ssq[bu][0] : ssq[bu][1]) + Wn + p;
        const float* aT = (fgT ? ssq[bu][2] : ssq[bu][3]) + Wn + p;
        float bp = aP[0];
        float bt = aT[0];

        #pragma unroll
        for (int d = 1; d <= 4; ++d) {
            float dd = (float)(d * d);
            bp = fminf(bp, dd + fminf(aP[-d], aP[d]));
            bt = fminf(bt, dd + fminf(aT[-d], aT[d]));
        }
        float bmax = fmaxf(bp, bt);
        if (bmax > 25.0f) {
            for (int d = 5; d < Wn; ++d) {
                float dd = (float)(d * d);
                if (dd >= bmax) break;
                bp = fminf(bp, dd + fminf(aP[-d], aP[d]));
                bt = fminf(bt, dd + fminf(aT[-d], aT[d]));
                bmax = fmaxf(bp, bt);
            }
        }

        // other-class D is exactly 0 -> field = sqrt(D_own)
        float pd = sqrtf(bp) * (float)(hp != 0);
        float td = sqrtf(bt) * (float)(ht != 0);

        float sg = 1.0f / (1.0f + __expf(-xs[r]));
        float e  = sg - tvs[r];
        e = e * e;

        float num = pd * pd + td * td;
        float den = pd + td;
        den = den * den;
        vsum += e * (num / den);
    }

    // single deterministic block reduction
    float v = vsum;
    #pragma unroll
    for (int o = 16; o > 0; o >>= 1)
        v += __shfl_down_sync(0xffffffffu, v, o);
    if ((p & 31) == 0) wsum[p >> 5] = v;
    __syncthreads();
    if (p == 0) {
        float s = 0.0f;
        #pragma unroll
        for (int i = 0; i < 6; ++i) s += wsum[i];
        __stcg(&g_part[blockIdx.x], s);
        unsigned ticket;
        asm volatile("atom.acq_rel.gpu.global.add.u32 %0, [%1], %2;"
                     : "=r"(ticket)
                     : "l"(&g_count), "r"(1u)
                     : "memory");
        s_last = (ticket == (unsigned)(gridDim.x - 1));
    }
    __syncthreads();

    // last finishing block: deterministic fixed-order fp64 final reduction.
    if (s_last) {
        double s = 0.0;
        for (int i = p; i < Bn * NSL; i += Wn)
            s += (double)__ldcg(&g_part[i]);
        dsm[p] = s;
        __syncthreads();
        #pragma unroll
        for (int o = 96; o >= 3; o >>= 1) {     // 192->96->...->3
            if (p < o) dsm[p] += dsm[p + o];
            __syncthreads();
        }
        if (p == 0) {
            double tot = dsm[0] + dsm[1] + dsm[2];
            out[0] = (float)(tot / (double)NTOT);
            g_count = 0;
        }
    }
}

extern "C" void kernel_launch(void* const* d_in, const int* in_sizes, int n_in,
                              void* d_out, int out_size) {
    const float* pred = (const float*)d_in[0];
    const float* tgt  = (const float*)d_in[1];
    float* out = (float*)d_out;
    (void)in_sizes; (void)n_in; (void)out_size;

    dim3 mb(Wn, 2);
    mask_kernel<<<2 * Bn * NCH, mb>>>(pred, tgt);
    rowpass_kernel<<<Bn * NSL, Wn>>>(pred, tgt, out);
}